// round 14
// baseline (speedup 1.0000x reference)
#include <cuda_runtime.h>
#include <cuda_fp16.h>
#include <cstdint>

#define N_NODES 4096
#define IN_FEAT 512
#define HEADS   8
#define HEAD_DIM 64
#define BAND    0.075f

// ---------------- scratch (static device globals: no allocation) ------------
__device__ float    g_Qh[HEADS * N_NODES * 64];  // head-major [h][node][d]
__device__ float    g_Kh[HEADS * N_NODES * 64];
__device__ float    g_KhT[HEADS * 64 * N_NODES]; // [h][d][node]  (rescan)
__device__ __half   g_Kp16[HEADS * 64 * 4096];   // fragment-PAIRED fp16 tile images
__device__ __half   g_xAhi[512 * 4096];          // A-frag images of x (hi), (nt,chunk)
__device__ __half   g_xAlo[512 * 4096];
__device__ __half   g_wBhi[3 * 64 * 4096];       // B-frag images of WQ|WK|WV (hi)
__device__ __half   g_wBlo[3 * 64 * 4096];
__device__ float    g_V[N_NODES * 512];          // node-major
__device__ unsigned g_adjbits[128 * N_NODES];    // [word][q]
__device__ float    g_maskE[64 * 64 * 8 * 512];  // acc-fragment-ordered mask bias (64MB)
__device__ int      g_argmax[HEADS * N_NODES];
__device__ int      g_fixcount;
__device__ int      g_fixlist[HEADS * N_NODES];

// ---------------- mbarrier + bulk-copy helpers --------------------------------
__device__ __forceinline__ uint32_t smem_u32(const void* p) {
    uint32_t a;
    asm("{ .reg .u64 t; cvta.to.shared.u64 t, %1; cvt.u32.u64 %0, t; }"
        : "=r"(a) : "l"(p));
    return a;
}
__device__ __forceinline__ void mbar_init(uint32_t bar, uint32_t cnt) {
    asm volatile("mbarrier.init.shared.b64 [%0], %1;" :: "r"(bar), "r"(cnt) : "memory");
}
__device__ __forceinline__ void mbar_arrive_expect(uint32_t bar, uint32_t bytes) {
    asm volatile("mbarrier.arrive.expect_tx.shared.b64 _, [%0], %1;"
                 :: "r"(bar), "r"(bytes) : "memory");
}
__device__ __forceinline__ void bulk_g2s(uint32_t dst, const void* src,
                                         uint32_t bytes, uint32_t bar) {
    asm volatile(
        "cp.async.bulk.shared::cluster.global.mbarrier::complete_tx::bytes "
        "[%0], [%1], %2, [%3];"
        :: "r"(dst), "l"(src), "r"(bytes), "r"(bar) : "memory");
}
__device__ __forceinline__ void mbar_wait(uint32_t bar, uint32_t parity) {
    asm volatile(
        "{\n\t"
        ".reg .pred P;\n\t"
        "WL_%=:\n\t"
        "mbarrier.try_wait.parity.acquire.cta.shared::cta.b64 P, [%0], %1, 0x989680;\n\t"
        "@P bra WD_%=;\n\t"
        "bra WL_%=;\n\t"
        "WD_%=:\n\t"
        "}"
        :: "r"(bar), "r"(parity) : "memory");
}

// ---------------- fp16 MMA helpers --------------------------------------------
__device__ __forceinline__ uint32_t pack_h2(float x, float y) {
    __half2 v = __floats2half2_rn(x, y);
    return *reinterpret_cast<uint32_t*>(&v);
}
__device__ __forceinline__ void mma16(float* d, const uint32_t* a,
                                      uint32_t b0, uint32_t b1) {
    asm("mma.sync.aligned.m16n8k16.row.col.f32.f16.f16.f32 "
        "{%0,%1,%2,%3}, {%4,%5,%6,%7}, {%8,%9}, {%0,%1,%2,%3};"
        : "+f"(d[0]), "+f"(d[1]), "+f"(d[2]), "+f"(d[3])
        : "r"(a[0]), "r"(a[1]), "r"(a[2]), "r"(a[3]), "r"(b0), "r"(b1));
}
__device__ __forceinline__ float f16lo(float x) {
    return x - __half2float(__float2half_rn(x));
}

// ============================================================================
// prep_all: ONE launch.
//   b < 512  : A-frag hi/lo images of x
//   b < 704  : B-frag hi/lo images of W{Q,K,V}
//   b < 1216 : adj -> bitmask (8 q rows per block)
// ============================================================================
__global__ __launch_bounds__(256) void prep_all(const float* __restrict__ x,
                                                const float* __restrict__ WQ,
                                                const float* __restrict__ WK,
                                                const float* __restrict__ WV,
                                                const int* __restrict__ adj) {
    const int b = blockIdx.x;
    if (b == 0 && threadIdx.x == 0) g_fixcount = 0;

    if (b < 512) {
        const int nt = b >> 3, c = b & 7;
        __half2* dhi = (__half2*)(g_xAhi + (size_t)b * 4096);
        __half2* dlo = (__half2*)(g_xAlo + (size_t)b * 4096);
#pragma unroll
        for (int rep = 0; rep < 2; rep++) {
            const int it   = rep * 256 + threadIdx.x;
            const int w    = it >> 7;
            const int s    = (it >> 5) & 3;
            const int lane = it & 31;
            const int g    = lane >> 2, l4 = lane & 3;
            const int n0 = nt * 64 + w * 16 + g;
            const int n1 = n0 + 8;
            const int k0 = c * 64 + s * 16 + l4 * 2;
            const float* p0 = x + (size_t)n0 * 512 + k0;
            const float* p1 = x + (size_t)n1 * 512 + k0;
            float v[8] = {p0[0], p0[1], p1[0], p1[1], p0[8], p0[9], p1[8], p1[9]};
            dhi[it * 4 + 0] = __floats2half2_rn(v[0], v[1]);
            dhi[it * 4 + 1] = __floats2half2_rn(v[2], v[3]);
            dhi[it * 4 + 2] = __floats2half2_rn(v[4], v[5]);
            dhi[it * 4 + 3] = __floats2half2_rn(v[6], v[7]);
            dlo[it * 4 + 0] = __floats2half2_rn(f16lo(v[0]), f16lo(v[1]));
            dlo[it * 4 + 1] = __floats2half2_rn(f16lo(v[2]), f16lo(v[3]));
            dlo[it * 4 + 2] = __floats2half2_rn(f16lo(v[4]), f16lo(v[5]));
            dlo[it * 4 + 3] = __floats2half2_rn(f16lo(v[6]), f16lo(v[7]));
        }
    } else if (b < 704) {
        const int b2 = b - 512;
        const int wsel = b2 >> 6;               // 0=Q,1=K,2=V
        const int r  = b2 & 63;
        const int ct = r >> 3, c = r & 7;
        const float* W = (wsel == 0) ? WQ : ((wsel == 1) ? WK : WV);
        __half2* dhi = (__half2*)(g_wBhi + (size_t)b2 * 4096);
        __half2* dlo = (__half2*)(g_wBlo + (size_t)b2 * 4096);
#pragma unroll
        for (int rep = 0; rep < 2; rep++) {
            const int it   = rep * 256 + threadIdx.x;
            const int lane = it & 31;
            const int sp   = (it >> 5) & 1;
            const int nf   = it >> 6;
            const int key  = nf * 8 + (lane >> 2);
            const int kc   = sp * 32 + (lane & 3) * 2;
            const float* p = W + (size_t)(ct * 64 + key) * 512 + c * 64 + kc;
            float v[8] = {p[0], p[1], p[8], p[9], p[16], p[17], p[24], p[25]};
            dhi[it * 4 + 0] = __floats2half2_rn(v[0], v[1]);
            dhi[it * 4 + 1] = __floats2half2_rn(v[2], v[3]);
            dhi[it * 4 + 2] = __floats2half2_rn(v[4], v[5]);
            dhi[it * 4 + 3] = __floats2half2_rn(v[6], v[7]);
            dlo[it * 4 + 0] = __floats2half2_rn(f16lo(v[0]), f16lo(v[1]));
            dlo[it * 4 + 1] = __floats2half2_rn(f16lo(v[2]), f16lo(v[3]));
            dlo[it * 4 + 2] = __floats2half2_rn(f16lo(v[4]), f16lo(v[5]));
            dlo[it * 4 + 3] = __floats2half2_rn(f16lo(v[6]), f16lo(v[7]));
        }
    } else {
        const int q = (b - 704) * 8 + (threadIdx.x >> 5);
        const int lane = threadIdx.x & 31;
        const int* row = adj + (size_t)q * N_NODES;
#pragma unroll 4
        for (int w = 0; w < 128; w++) {
            unsigned m = __ballot_sync(0xffffffffu, row[w * 32 + lane] > 0);
            if (lane == 0) g_adjbits[w * N_NODES + q] = m;
        }
    }
}

// ============================================================================
// mask_expand: adjbits -> acc-fragment-ordered fp32 bias (0 / -3e38).
// Layout: g_maskE[((qt*64+t)*8 + nf)*512 + tid*4 + c]  == acc[nf][c] of thread tid.
// ============================================================================
__global__ __launch_bounds__(128) void mask_expand() {
    const int qt = blockIdx.x;       // 0..63
    const int tg = blockIdx.y;       // 0..7
    const int tid = threadIdx.x;
    const int w = tid >> 5, lane = tid & 31, g = lane >> 2, l4 = lane & 3;
    const int qA = qt * 64 + w * 16 + g;
    const int qB = qA + 8;

#pragma unroll
    for (int tt = 0; tt < 8; tt++) {
        const int t = tg * 8 + tt;
        const unsigned w0A = g_adjbits[(size_t)(2 * t)     * N_NODES + qA];
        const unsigned w1A = g_adjbits[(size_t)(2 * t + 1) * N_NODES + qA];
        const unsigned w0B = g_adjbits[(size_t)(2 * t)     * N_NODES + qB];
        const unsigned w1B = g_adjbits[(size_t)(2 * t + 1) * N_NODES + qB];
        float4* dst = (float4*)(g_maskE + ((size_t)(qt * 64 + t) * 8) * 512);
#pragma unroll
        for (int nf = 0; nf < 8; nf++) {
            const unsigned wdA = (nf < 4) ? w0A : w1A;
            const unsigned wdB = (nf < 4) ? w0B : w1B;
            const int sh = (nf & 3) * 8 + l4 * 2;
            float4 v;
            v.x = ((wdA >> sh) & 1u)       ? 0.0f : -3e38f;
            v.y = ((wdA >> (sh + 1)) & 1u) ? 0.0f : -3e38f;
            v.z = ((wdB >> sh) & 1u)       ? 0.0f : -3e38f;
            v.w = ((wdB >> (sh + 1)) & 1u) ? 0.0f : -3e38f;
            dst[nf * 128 + tid] = v;
        }
    }
}

// ============================================================================
// proj_mma: Q|K|V = x @ W^T via 3-chain split-fp16 MMA (validated R12/R13).
// ============================================================================
#define VM_SMEM (2 * 4 * 8192)

__global__ __launch_bounds__(128, 1) void proj_mma() {
    extern __shared__ __half vsm[];
    __shared__ __align__(8) unsigned long long s_bar[2];

    const int tid  = threadIdx.x;
    const int w    = tid >> 5;
    const int lane = tid & 31;
    const int g    = lane >> 2;
    const int l4   = lane & 3;
    const int nt   = blockIdx.x;
    const int ct   = blockIdx.y;
    const int wsel = ct >> 3;
    const int ct8  = ct & 7;

    const uint32_t bar0 = smem_u32(&s_bar[0]);
    const uint32_t bar1 = smem_u32(&s_bar[1]);
    if (tid == 0) { mbar_init(bar0, 1); mbar_init(bar1, 1); }
    __syncthreads();

    auto issue = [&](int c) {
        const int slot = c & 1;
        const uint32_t bar = slot ? bar1 : bar0;
        __half* base = vsm + (size_t)slot * 4 * 4096;
        const size_t bi = (size_t)((wsel * 8 + ct8) * 8 + c) * 4096;
        mbar_arrive_expect(bar, 32768);
        bulk_g2s(smem_u32(base),            g_xAhi + (size_t)(nt * 8 + c) * 4096, 8192, bar);
        bulk_g2s(smem_u32(base + 4096),     g_xAlo + (size_t)(nt * 8 + c) * 4096, 8192, bar);
        bulk_g2s(smem_u32(base + 2 * 4096), g_wBhi + bi, 8192, bar);
        bulk_g2s(smem_u32(base + 3 * 4096), g_wBlo + bi, 8192, bar);
    };
    if (tid == 0) { issue(0); issue(1); }

    float acc[8][4];
#pragma unroll
    for (int nf = 0; nf < 8; nf++)
#pragma unroll
        for (int j = 0; j < 4; j++) acc[nf][j] = 0.f;

    for (int c = 0; c < 8; c++) {
        const int slot = c & 1;
        mbar_wait(slot ? bar1 : bar0, (c >> 1) & 1);
        const __half* Ah = vsm + (size_t)slot * 4 * 4096;
        const __half* Al = Ah + 4096;
        const __half* Bh = Ah + 2 * 4096;
        const __half* Bl = Ah + 3 * 4096;

        uint32_t ah[4][4], al[4][4];
#pragma unroll
        for (int s = 0; s < 4; s++) {
            const uint4 vh = *(const uint4*)&Ah[((w * 4 + s) * 32 + lane) * 8];
            ah[s][0] = vh.x; ah[s][1] = vh.y; ah[s][2] = vh.z; ah[s][3] = vh.w;
            const uint4 vl = *(const uint4*)&Al[((w * 4 + s) * 32 + lane) * 8];
            al[s][0] = vl.x; al[s][1] = vl.y; al[s][2] = vl.z; al[s][3] = vl.w;
        }

#pragma unroll
        for (int nf = 0; nf < 8; nf++) {
#pragma unroll
            for (int sp = 0; sp < 2; sp++) {
                const uint4 bh = *(const uint4*)&Bh[(size_t)(((nf * 2 + sp) * 32 + lane)) * 8];
                const uint4 bl = *(const uint4*)&Bl[(size_t)(((nf * 2 + sp) * 32 + lane)) * 8];
                mma16(acc[nf], ah[2 * sp],     bh.x, bh.y);
                mma16(acc[nf], ah[2 * sp + 1], bh.z, bh.w);
                mma16(acc[nf], al[2 * sp],     bh.x, bh.y);
                mma16(acc[nf], al[2 * sp + 1], bh.z, bh.w);
                mma16(acc[nf], ah[2 * sp],     bl.x, bl.y);
                mma16(acc[nf], ah[2 * sp + 1], bl.z, bl.w);
            }
        }
        __syncthreads();
        if (tid == 0 && c + 2 < 8) issue(c + 2);
    }

    const int n0 = nt * 64 + w * 16 + g;
    const int n1 = n0 + 8;

    if (wsel == 2) {
#pragma unroll
        for (int nf = 0; nf < 8; nf++) {
            const int colv = ct8 * 64 + nf * 8 + l4 * 2;
            *(float2*)&g_V[(size_t)n0 * 512 + colv] = make_float2(acc[nf][0], acc[nf][1]);
            *(float2*)&g_V[(size_t)n1 * 512 + colv] = make_float2(acc[nf][2], acc[nf][3]);
        }
    } else {
        float* dst = ((wsel == 0) ? g_Qh : g_Kh) + (size_t)ct8 * N_NODES * 64;
#pragma unroll
        for (int nf = 0; nf < 8; nf++) {
            const int d = nf * 8 + l4 * 2;
            *(float2*)&dst[(size_t)n0 * 64 + d] = make_float2(acc[nf][0], acc[nf][1]);
            *(float2*)&dst[(size_t)n1 * 64 + d] = make_float2(acc[nf][2], acc[nf][3]);
        }
        if (wsel == 1) {
            __half2* img = (__half2*)(g_Kp16 + (size_t)(ct8 * 64 + nt) * 4096);
#pragma unroll
            for (int nf = 0; nf < 8; nf++) {
                const int jj  = nf & 3;
                const int sp_ = nf >> 2;
                const int kk0 = w * 16 + g;
                const int kk1 = kk0 + 8;
                const int lane0 = ((kk0 & 7) << 2) | l4;
                const int lane1 = ((kk1 & 7) << 2) | l4;
                const int idx0 = (((kk0 >> 3) * 2 + sp_) * 32 + lane0) * 4 + jj;
                const int idx1 = (((kk1 >> 3) * 2 + sp_) * 32 + lane1) * 4 + jj;
                img[idx0] = __floats2half2_rn(acc[nf][0], acc[nf][1]);
                img[idx1] = __floats2half2_rn(acc[nf][2], acc[nf][3]);
            }
        }
    }
}

// ============================================================================
// K transpose for rescan
// ============================================================================
__global__ __launch_bounds__(256) void transpose_k() {
    __shared__ float t[32][33];
    const int h  = blockIdx.z;
    const int d0 = blockIdx.y * 32;
    const int n0 = blockIdx.x * 32;
    const int txx = threadIdx.x, tyy = threadIdx.y;
    const float* src = g_Kh + (size_t)h * N_NODES * 64;
#pragma unroll
    for (int i = tyy; i < 32; i += 8)
        t[i][txx] = src[(size_t)(n0 + i) * 64 + d0 + txx];
    __syncthreads();
    float* dst = g_KhT + (size_t)h * 64 * N_NODES;
#pragma unroll
    for (int i = tyy; i < 32; i += 8)
        dst[(size_t)(d0 + i) * N_NODES + n0 + txx] = t[txx][i];
}

// ============================================================================
// rare index recovery (validated)
// ============================================================================
__device__ __forceinline__ void rare2(const float (&acc)[8][4], int cofs,
                                      int t, int l4, float tmax,
                                      float& best, float& best2, int& bk) {
    float sec = -3e38f;
    int   idx = bk;
    bool  taken = false;
#pragma unroll
    for (int nf = 0; nf < 8; nf++)
#pragma unroll
        for (int c = 0; c < 2; c++) {
            const float v = acc[nf][cofs + c];
            if (v == tmax && !taken) {
                taken = true;
                idx = t * 64 + nf * 8 + l4 * 2 + c;
            } else {
                sec = fmaxf(sec, v);
            }
        }
    best2 = fmaxf(best2, fmaxf(best, sec));
    best  = tmax;
    bk    = idx;
}

// ============================================================================
// Score argmax via mma.sync m16n8k16.f16; mask bias LOADED straight into the
// accumulators from g_maskE (8 coalesced LDG.128, issued before mbar_wait).
// ============================================================================
__global__ __launch_bounds__(128, 4) void score_mma() {
    __shared__ __align__(16) __half sK[4][4096];
    __shared__ __align__(8) unsigned long long s_bar[4];

    const int tid  = threadIdx.x;
    const int w    = tid >> 5;
    const int lane = tid & 31;
    const int g    = lane >> 2;
    const int l4   = lane & 3;
    const int h    = blockIdx.y;
    const int qt   = blockIdx.x;
    const int qA   = qt * 64 + w * 16 + g;
    const int qB   = qA + 8;

    uint32_t bar[4];
#pragma unroll
    for (int i = 0; i < 4; i++) bar[i] = smem_u32(&s_bar[i]);
    const __half* Ksrc = g_Kp16 + (size_t)h * 64 * 4096;
    const float4* Mbase = (const float4*)(g_maskE + ((size_t)qt * 64 * 8) * 512);

    if (tid == 0) {
#pragma unroll
        for (int i = 0; i < 4; i++) mbar_init(bar[i], 1);
    }
    __syncthreads();

    if (tid == 0) {
#pragma unroll
        for (int i = 0; i < 4; i++) {
            mbar_arrive_expect(bar[i], 8192);
            bulk_g2s(smem_u32(&sK[i][0]), Ksrc + (size_t)i * 4096, 8192, bar[i]);
        }
    }

    uint32_t a[4][4];
    {
        const float* QA = g_Qh + ((size_t)h * N_NODES + qA) * 64;
        const float* QB = QA + 8 * 64;
#pragma unroll
        for (int s = 0; s < 4; s++) {
            const int c = s * 16 + 2 * l4;
            a[s][0] = pack_h2(QA[c],     QA[c + 1]);
            a[s][1] = pack_h2(QB[c],     QB[c + 1]);
            a[s][2] = pack_h2(QA[c + 8], QA[c + 9]);
            a[s][3] = pack_h2(QB[c + 8], QB[c + 9]);
        }
    }

    float bestA = -3.3e38f, best2A = -3.3e38f;
    float bestB = -3.3e38f, best2B = -3.3e38f;
    int   bkA = 0, bkB = 0;

    for (int t = 0; t < 64; t++) {
        const int buf = t & 3;
        const int ph  = (t >> 2) & 1;

        // mask bias -> accumulators (coalesced; latency hidden under mbar_wait)
        const float4* mrow = Mbase + (size_t)t * 8 * 128;
        float acc[8][4];
#pragma unroll
        for (int nf = 0; nf < 8; nf++) {
            const float4 m = mrow[nf * 128 + tid];
            acc[nf][0] = m.x; acc[nf][1] = m.y;
            acc[nf][2] = m.z; acc[nf][3] = m.w;
        }

        mbar_wait(bar[buf], ph);
        const __half* kb = &sK[buf][0];
#pragma unroll
        for (int nf = 0; nf < 8; nf++) {
#pragma unroll
            for (int sp = 0; sp < 2; sp++) {
                const uint4 bb = *(const uint4*)&kb[(size_t)(((nf * 2 + sp) * 32 + lane)) * 8];
                mma16(acc[nf], a[2 * sp],     bb.x, bb.y);
                mma16(acc[nf], a[2 * sp + 1], bb.z, bb.w);
            }
        }
        __syncthreads();
        if (tid == 0 && t + 4 < 64) {
            mbar_arrive_expect(bar[buf], 8192);
            bulk_g2s(smem_u32(&sK[buf][0]), Ksrc + (size_t)(t + 4) * 4096, 8192, bar[buf]);
        }

        float tA = fmaxf(acc[0][0], acc[0][1]);
        float tB = fmaxf(acc[0][2], acc[0][3]);
#pragma unroll
        for (int nf = 1; nf < 8; nf++) {
            tA = fmaxf(tA, fmaxf(acc[nf][0], acc[nf][1]));
            tB = fmaxf(tB, fmaxf(acc[nf][2], acc[nf][3]));
        }
        if (tA > bestA) rare2(acc, 0, t, l4, tA, bestA, best2A, bkA);
        else            best2A = fmaxf(best2A, tA);
        if (tB > bestB) rare2(acc, 2, t, l4, tB, bestB, best2B, bkB);
        else            best2B = fmaxf(best2B, tB);
    }

#pragma unroll
    for (int off = 1; off < 4; off <<= 1) {
        float ob  = __shfl_xor_sync(0xffffffffu, bestA, off);
        int   obk = __shfl_xor_sync(0xffffffffu, bkA,  off);
        float ob2 = __shfl_xor_sync(0xffffffffu, best2A, off);
        best2A = fmaxf(fmaxf(best2A, ob2), fminf(bestA, ob));
        if (ob > bestA || (ob == bestA && obk < bkA)) { bestA = ob; bkA = obk; }

        ob  = __shfl_xor_sync(0xffffffffu, bestB, off);
        obk = __shfl_xor_sync(0xffffffffu, bkB,  off);
        ob2 = __shfl_xor_sync(0xffffffffu, best2B, off);
        best2B = fmaxf(fmaxf(best2B, ob2), fminf(bestB, ob));
        if (ob > bestB || (ob == bestB && obk < bkB)) { bestB = ob; bkB = obk; }
    }

    if (l4 == 0) {
        const int hqA = h * N_NODES + qA;
        const int hqB = h * N_NODES + qB;
        g_argmax[hqA] = bkA;
        g_argmax[hqB] = bkB;
        if (bestA - best2A < BAND) g_fixlist[atomicAdd(&g_fixcount, 1)] = hqA;
        if (bestB - best2B < BAND) g_fixlist[atomicAdd(&g_fixcount, 1)] = hqB;
    }
}

// ============================================================================
// Pass 2: exact fp32 re-argmax of flagged rows — coalesced via K^T.
// ============================================================================
__global__ __launch_bounds__(512) void rescan() {
    __shared__ float sq[64];
    __shared__ float s_best[16];
    __shared__ int   s_bk[16];
    const int nfix = g_fixcount;
    const int tid = threadIdx.x, lane = tid & 31, wrp = tid >> 5;

    for (int i = blockIdx.x; i < nfix; i += gridDim.x) {
        const int hq = g_fixlist[i];
        const int h = hq >> 12, q = hq & (N_NODES - 1);
        if (tid < 64) sq[tid] = g_Qh[((size_t)h * N_NODES + q) * 64 + tid];
        __syncthreads();

        const float4* KT = (const float4*)(g_KhT + (size_t)h * 64 * N_NODES);
        float acc[8] = {0.f, 0.f, 0.f, 0.f, 0.f, 0.f, 0.f, 0.f};
#pragma unroll 4
        for (int d = 0; d < 64; d++) {
            const float qd = sq[d];
            const float4 v0 = KT[(size_t)d * 1024 + tid];
            const float4 v1 = KT[(size_t)d * 1024 + 512 + tid];
            acc[0] += qd * v0.x; acc[1] += qd * v0.y;
            acc[2] += qd * v0.z; acc[3] += qd * v0.w;
            acc[4] += qd * v1.x; acc[5] += qd * v1.y;
            acc[6] += qd * v1.z; acc[7] += qd * v1.w;
        }

        const int k0 = tid * 4, k1 = 2048 + tid * 4;
        const unsigned w0 = g_adjbits[(size_t)(k0 >> 5) * N_NODES + q];
        const unsigned w1 = g_adjbits[(size_t)(k1 >> 5) * N_NODES + q];
        float best = -3e38f;
        int   bk   = 1 << 30;
#pragma unroll
        for (int j = 0; j < 4; j++) {
            if ((w0 >> ((k0 + j) & 31)) & 1u)
                if (acc[j] > best) { best = acc[j]; bk = k0 + j; }
        }
#pragma unroll
        for (int j = 0; j < 4; j++) {
            if ((w1 >> ((k1 + j) & 31)) & 1u)
                if (acc[4 + j] > best) { best = acc[4 + j]; bk = k1 + j; }
        }
#pragma unroll
        for (int off = 16; off > 0; off >>= 1) {
            float ob  = __shfl_xor_sync(0xffffffffu, best, off);
            int   obk = __shfl_xor_sync(0xffffffffu, bk, off);
            if (ob > best || (ob == best && obk < bk)) { best = ob; bk = obk; }
        }
        if (lane == 0) { s_best[wrp] = best; s_bk[wrp] = bk; }
        __syncthreads();
        if (tid == 0) {
            float b = s_best[0]; int k = s_bk[0];
#pragma unroll
            for (int j = 1; j < 16; j++)
                if (s_best[j] > b || (s_best[j] == b && s_bk[j] < k)) {
                    b = s_best[j]; k = s_bk[j];
                }
            g_argmax[hq] = k;
        }
        __syncthreads();
    }
}

// ============================================================================
// out[q, h*64+d] = V[argmax(h,q), h*64+d] / HEADS
// ============================================================================
__global__ __launch_bounds__(256) void gather_out(float* __restrict__ out) {
    const int idx = blockIdx.x * blockDim.x + threadIdx.x;
    const int q   = idx >> 7;
    const int c4  = idx & 127;
    const int h   = c4 >> 4;
    const int k   = g_argmax[h * N_NODES + q];
    float4 t = *(const float4*)&g_V[(size_t)k * 512 + c4 * 4];
    float4 v = make_float4(t.x * 0.125f, t.y * 0.125f, t.z * 0.125f, t.w * 0.125f);
    *(float4*)&out[(size_t)idx * 4] = v;
}

// ============================================================================
extern "C" void kernel_launch(void* const* d_in, const int* in_sizes, int n_in,
                              void* d_out, int out_size)
{
    const float* x   = (const float*)d_in[0];
    const int*   adj = (const int*)d_in[1];
    const float* WQ  = (const float*)d_in[2];
    const float* WK  = (const float*)d_in[3];
    const float* WV  = (const float*)d_in[4];
    float* out = (float*)d_out;

    cudaFuncSetAttribute(proj_mma,
                         cudaFuncAttributeMaxDynamicSharedMemorySize, VM_SMEM);

    prep_all<<<1216, 256>>>(x, WQ, WK, WV, adj);

    mask_expand<<<dim3(64, 8), 128>>>();

    proj_mma<<<dim3(64, 24), 128, VM_SMEM>>>();

    dim3 tb(32, 8);
    transpose_k<<<dim3(N_NODES / 32, 2, HEADS), tb>>>();

    score_mma<<<dim3(N_NODES / 64, HEADS), 128>>>();

    rescan<<<512, 512>>>();

    gather_out<<<(N_NODES * 512 / 4) / 256, 256>>>(out);
}

// round 15
// speedup vs baseline: 1.0820x; 1.0820x over previous
#include <cuda_runtime.h>
#include <cuda_fp16.h>
#include <cstdint>

#define N_NODES 4096
#define IN_FEAT 512
#define HEADS   8
#define HEAD_DIM 64
#define BAND    0.075f

// ---------------- scratch (static device globals: no allocation) ------------
__device__ float    g_Qh[HEADS * N_NODES * 64];  // head-major [h][node][d]
__device__ float    g_KhT[HEADS * 64 * N_NODES]; // [h][d][node]  (rescan)
__device__ __half   g_Kp16[HEADS * 64 * 4096];   // fragment-PAIRED fp16 tile images
__device__ __half   g_xAhi[512 * 4096];          // A-frag images of x (hi), (nt,chunk)
__device__ __half   g_xAlo[512 * 4096];
__device__ __half   g_wBhi[3 * 64 * 4096];       // B-frag images of WQ|WK|WV (hi)
__device__ __half   g_wBlo[3 * 64 * 4096];
__device__ float    g_V[N_NODES * 512];          // node-major
__device__ unsigned g_adjbits[128 * N_NODES];    // [word][q]
__device__ int      g_argmax[HEADS * N_NODES];
__device__ int      g_fixcount;
__device__ int      g_fixlist[HEADS * N_NODES];

// ---------------- mbarrier + bulk-copy helpers --------------------------------
__device__ __forceinline__ uint32_t smem_u32(const void* p) {
    uint32_t a;
    asm("{ .reg .u64 t; cvta.to.shared.u64 t, %1; cvt.u32.u64 %0, t; }"
        : "=r"(a) : "l"(p));
    return a;
}
__device__ __forceinline__ void mbar_init(uint32_t bar, uint32_t cnt) {
    asm volatile("mbarrier.init.shared.b64 [%0], %1;" :: "r"(bar), "r"(cnt) : "memory");
}
__device__ __forceinline__ void mbar_arrive_expect(uint32_t bar, uint32_t bytes) {
    asm volatile("mbarrier.arrive.expect_tx.shared.b64 _, [%0], %1;"
                 :: "r"(bar), "r"(bytes) : "memory");
}
__device__ __forceinline__ void bulk_g2s(uint32_t dst, const void* src,
                                         uint32_t bytes, uint32_t bar) {
    asm volatile(
        "cp.async.bulk.shared::cluster.global.mbarrier::complete_tx::bytes "
        "[%0], [%1], %2, [%3];"
        :: "r"(dst), "l"(src), "r"(bytes), "r"(bar) : "memory");
}
__device__ __forceinline__ void mbar_wait(uint32_t bar, uint32_t parity) {
    asm volatile(
        "{\n\t"
        ".reg .pred P;\n\t"
        "WL_%=:\n\t"
        "mbarrier.try_wait.parity.acquire.cta.shared::cta.b64 P, [%0], %1, 0x989680;\n\t"
        "@P bra WD_%=;\n\t"
        "bra WL_%=;\n\t"
        "WD_%=:\n\t"
        "}"
        :: "r"(bar), "r"(parity) : "memory");
}

// ---------------- fp16 MMA helpers --------------------------------------------
__device__ __forceinline__ uint32_t pack_h2(float x, float y) {
    __half2 v = __floats2half2_rn(x, y);
    return *reinterpret_cast<uint32_t*>(&v);
}
__device__ __forceinline__ void mma16(float* d, const uint32_t* a,
                                      uint32_t b0, uint32_t b1) {
    asm("mma.sync.aligned.m16n8k16.row.col.f32.f16.f16.f32 "
        "{%0,%1,%2,%3}, {%4,%5,%6,%7}, {%8,%9}, {%0,%1,%2,%3};"
        : "+f"(d[0]), "+f"(d[1]), "+f"(d[2]), "+f"(d[3])
        : "r"(a[0]), "r"(a[1]), "r"(a[2]), "r"(a[3]), "r"(b0), "r"(b1));
}
__device__ __forceinline__ float f16lo(float x) {
    return x - __half2float(__float2half_rn(x));
}

// ============================================================================
// prep_all: ONE launch.
//   b < 512  : A-frag hi/lo images of x
//   b < 704  : B-frag hi/lo images of W{Q,K,V}
//   b < 1216 : adj -> bitmask (8 q rows per block)
// ============================================================================
__global__ __launch_bounds__(256) void prep_all(const float* __restrict__ x,
                                                const float* __restrict__ WQ,
                                                const float* __restrict__ WK,
                                                const float* __restrict__ WV,
                                                const int* __restrict__ adj) {
    const int b = blockIdx.x;
    if (b == 0 && threadIdx.x == 0) g_fixcount = 0;

    if (b < 512) {
        const int nt = b >> 3, c = b & 7;
        __half2* dhi = (__half2*)(g_xAhi + (size_t)b * 4096);
        __half2* dlo = (__half2*)(g_xAlo + (size_t)b * 4096);
#pragma unroll
        for (int rep = 0; rep < 2; rep++) {
            const int it   = rep * 256 + threadIdx.x;
            const int w    = it >> 7;
            const int s    = (it >> 5) & 3;
            const int lane = it & 31;
            const int g    = lane >> 2, l4 = lane & 3;
            const int n0 = nt * 64 + w * 16 + g;
            const int n1 = n0 + 8;
            const int k0 = c * 64 + s * 16 + l4 * 2;
            const float* p0 = x + (size_t)n0 * 512 + k0;
            const float* p1 = x + (size_t)n1 * 512 + k0;
            float v[8] = {p0[0], p0[1], p1[0], p1[1], p0[8], p0[9], p1[8], p1[9]};
            dhi[it * 4 + 0] = __floats2half2_rn(v[0], v[1]);
            dhi[it * 4 + 1] = __floats2half2_rn(v[2], v[3]);
            dhi[it * 4 + 2] = __floats2half2_rn(v[4], v[5]);
            dhi[it * 4 + 3] = __floats2half2_rn(v[6], v[7]);
            dlo[it * 4 + 0] = __floats2half2_rn(f16lo(v[0]), f16lo(v[1]));
            dlo[it * 4 + 1] = __floats2half2_rn(f16lo(v[2]), f16lo(v[3]));
            dlo[it * 4 + 2] = __floats2half2_rn(f16lo(v[4]), f16lo(v[5]));
            dlo[it * 4 + 3] = __floats2half2_rn(f16lo(v[6]), f16lo(v[7]));
        }
    } else if (b < 704) {
        const int b2 = b - 512;
        const int wsel = b2 >> 6;               // 0=Q,1=K,2=V
        const int r  = b2 & 63;
        const int ct = r >> 3, c = r & 7;
        const float* W = (wsel == 0) ? WQ : ((wsel == 1) ? WK : WV);
        __half2* dhi = (__half2*)(g_wBhi + (size_t)b2 * 4096);
        __half2* dlo = (__half2*)(g_wBlo + (size_t)b2 * 4096);
#pragma unroll
        for (int rep = 0; rep < 2; rep++) {
            const int it   = rep * 256 + threadIdx.x;
            const int lane = it & 31;
            const int sp   = (it >> 5) & 1;
            const int nf   = it >> 6;
            const int key  = nf * 8 + (lane >> 2);
            const int kc   = sp * 32 + (lane & 3) * 2;
            const float* p = W + (size_t)(ct * 64 + key) * 512 + c * 64 + kc;
            float v[8] = {p[0], p[1], p[8], p[9], p[16], p[17], p[24], p[25]};
            dhi[it * 4 + 0] = __floats2half2_rn(v[0], v[1]);
            dhi[it * 4 + 1] = __floats2half2_rn(v[2], v[3]);
            dhi[it * 4 + 2] = __floats2half2_rn(v[4], v[5]);
            dhi[it * 4 + 3] = __floats2half2_rn(v[6], v[7]);
            dlo[it * 4 + 0] = __floats2half2_rn(f16lo(v[0]), f16lo(v[1]));
            dlo[it * 4 + 1] = __floats2half2_rn(f16lo(v[2]), f16lo(v[3]));
            dlo[it * 4 + 2] = __floats2half2_rn(f16lo(v[4]), f16lo(v[5]));
            dlo[it * 4 + 3] = __floats2half2_rn(f16lo(v[6]), f16lo(v[7]));
        }
    } else {
        const int q = (b - 704) * 8 + (threadIdx.x >> 5);
        const int lane = threadIdx.x & 31;
        const int* row = adj + (size_t)q * N_NODES;
#pragma unroll 4
        for (int w = 0; w < 128; w++) {
            unsigned m = __ballot_sync(0xffffffffu, row[w * 32 + lane] > 0);
            if (lane == 0) g_adjbits[w * N_NODES + q] = m;
        }
    }
}

// ============================================================================
// proj_mma: Q|K|V = x @ W^T via 3-chain split-fp16 MMA.
// Grid (nt 64, ct 24): ct 0-7 -> Q, 8-15 -> K (+Kp16 image +KhT), 16-23 -> V.
// ============================================================================
#define VM_SMEM (2 * 4 * 8192)

__global__ __launch_bounds__(128, 1) void proj_mma() {
    extern __shared__ __half vsm[];
    __shared__ __align__(8) unsigned long long s_bar[2];

    const int tid  = threadIdx.x;
    const int w    = tid >> 5;
    const int lane = tid & 31;
    const int g    = lane >> 2;
    const int l4   = lane & 3;
    const int nt   = blockIdx.x;
    const int ct   = blockIdx.y;
    const int wsel = ct >> 3;
    const int ct8  = ct & 7;

    const uint32_t bar0 = smem_u32(&s_bar[0]);
    const uint32_t bar1 = smem_u32(&s_bar[1]);
    if (tid == 0) { mbar_init(bar0, 1); mbar_init(bar1, 1); }
    __syncthreads();

    auto issue = [&](int c) {
        const int slot = c & 1;
        const uint32_t bar = slot ? bar1 : bar0;
        __half* base = vsm + (size_t)slot * 4 * 4096;
        const size_t bi = (size_t)((wsel * 8 + ct8) * 8 + c) * 4096;
        mbar_arrive_expect(bar, 32768);
        bulk_g2s(smem_u32(base),            g_xAhi + (size_t)(nt * 8 + c) * 4096, 8192, bar);
        bulk_g2s(smem_u32(base + 4096),     g_xAlo + (size_t)(nt * 8 + c) * 4096, 8192, bar);
        bulk_g2s(smem_u32(base + 2 * 4096), g_wBhi + bi, 8192, bar);
        bulk_g2s(smem_u32(base + 3 * 4096), g_wBlo + bi, 8192, bar);
    };
    if (tid == 0) { issue(0); issue(1); }

    float acc[8][4];
#pragma unroll
    for (int nf = 0; nf < 8; nf++)
#pragma unroll
        for (int j = 0; j < 4; j++) acc[nf][j] = 0.f;

    for (int c = 0; c < 8; c++) {
        const int slot = c & 1;
        mbar_wait(slot ? bar1 : bar0, (c >> 1) & 1);
        const __half* Ah = vsm + (size_t)slot * 4 * 4096;
        const __half* Al = Ah + 4096;
        const __half* Bh = Ah + 2 * 4096;
        const __half* Bl = Ah + 3 * 4096;

        uint32_t ah[4][4], al[4][4];
#pragma unroll
        for (int s = 0; s < 4; s++) {
            const uint4 vh = *(const uint4*)&Ah[((w * 4 + s) * 32 + lane) * 8];
            ah[s][0] = vh.x; ah[s][1] = vh.y; ah[s][2] = vh.z; ah[s][3] = vh.w;
            const uint4 vl = *(const uint4*)&Al[((w * 4 + s) * 32 + lane) * 8];
            al[s][0] = vl.x; al[s][1] = vl.y; al[s][2] = vl.z; al[s][3] = vl.w;
        }

#pragma unroll
        for (int nf = 0; nf < 8; nf++) {
#pragma unroll
            for (int sp = 0; sp < 2; sp++) {
                const uint4 bh = *(const uint4*)&Bh[(size_t)(((nf * 2 + sp) * 32 + lane)) * 8];
                const uint4 bl = *(const uint4*)&Bl[(size_t)(((nf * 2 + sp) * 32 + lane)) * 8];
                mma16(acc[nf], ah[2 * sp],     bh.x, bh.y);
                mma16(acc[nf], ah[2 * sp + 1], bh.z, bh.w);
                mma16(acc[nf], al[2 * sp],     bh.x, bh.y);
                mma16(acc[nf], al[2 * sp + 1], bh.z, bh.w);
                mma16(acc[nf], ah[2 * sp],     bl.x, bl.y);
                mma16(acc[nf], ah[2 * sp + 1], bl.z, bl.w);
            }
        }
        __syncthreads();
        if (tid == 0 && c + 2 < 8) issue(c + 2);
    }

    const int n0 = nt * 64 + w * 16 + g;
    const int n1 = n0 + 8;

    if (wsel == 2) {
        // V: node-major [node][512]
#pragma unroll
        for (int nf = 0; nf < 8; nf++) {
            const int colv = ct8 * 64 + nf * 8 + l4 * 2;
            *(float2*)&g_V[(size_t)n0 * 512 + colv] = make_float2(acc[nf][0], acc[nf][1]);
            *(float2*)&g_V[(size_t)n1 * 512 + colv] = make_float2(acc[nf][2], acc[nf][3]);
        }
    } else if (wsel == 0) {
        // Q: head-major [h][node][d]
        float* dst = g_Qh + (size_t)ct8 * N_NODES * 64;
#pragma unroll
        for (int nf = 0; nf < 8; nf++) {
            const int d = nf * 8 + l4 * 2;
            *(float2*)&dst[(size_t)n0 * 64 + d] = make_float2(acc[nf][0], acc[nf][1]);
            *(float2*)&dst[(size_t)n1 * 64 + d] = make_float2(acc[nf][2], acc[nf][3]);
        }
    } else {
        // K: Kp16 fragment image (score) + KhT transposed fp32 (rescan)
        __half2* img = (__half2*)(g_Kp16 + (size_t)(ct8 * 64 + nt) * 4096);
        float*   kt  = g_KhT + (size_t)ct8 * 64 * N_NODES;
#pragma unroll
        for (int nf = 0; nf < 8; nf++) {
            const int jj  = nf & 3;
            const int sp_ = nf >> 2;
            const int kk0 = w * 16 + g;
            const int kk1 = kk0 + 8;
            const int lane0 = ((kk0 & 7) << 2) | l4;
            const int lane1 = ((kk1 & 7) << 2) | l4;
            const int idx0 = (((kk0 >> 3) * 2 + sp_) * 32 + lane0) * 4 + jj;
            const int idx1 = (((kk1 >> 3) * 2 + sp_) * 32 + lane1) * 4 + jj;
            img[idx0] = __floats2half2_rn(acc[nf][0], acc[nf][1]);
            img[idx1] = __floats2half2_rn(acc[nf][2], acc[nf][3]);

            const int d = nf * 8 + l4 * 2;
            kt[(size_t)d * N_NODES + n0]       = acc[nf][0];
            kt[(size_t)(d + 1) * N_NODES + n0] = acc[nf][1];
            kt[(size_t)d * N_NODES + n1]       = acc[nf][2];
            kt[(size_t)(d + 1) * N_NODES + n1] = acc[nf][3];
        }
    }
}

// ============================================================================
// rare index recovery (validated)
// ============================================================================
__device__ __forceinline__ void rare2(const float (&acc)[8][4], int cofs,
                                      int t, int l4, float tmax,
                                      float& best, float& best2, int& bk) {
    float sec = -3e38f;
    int   idx = bk;
    bool  taken = false;
#pragma unroll
    for (int nf = 0; nf < 8; nf++)
#pragma unroll
        for (int c = 0; c < 2; c++) {
            const float v = acc[nf][cofs + c];
            if (v == tmax && !taken) {
                taken = true;
                idx = t * 64 + nf * 8 + l4 * 2 + c;
            } else {
                sec = fmaxf(sec, v);
            }
        }
    best2 = fmaxf(best2, fmaxf(best, sec));
    best  = tmax;
    bk    = idx;
}

// ============================================================================
// Score argmax via mma.sync m16n8k16.f16 (R13 version: in-register mask
// expansion from adjbits, words prefetched 1 tile ahead).
// ============================================================================
__global__ __launch_bounds__(128, 4) void score_mma() {
    __shared__ __align__(16) __half sK[4][4096];
    __shared__ __align__(8) unsigned long long s_bar[4];

    const int tid  = threadIdx.x;
    const int w    = tid >> 5;
    const int lane = tid & 31;
    const int g    = lane >> 2;
    const int l4   = lane & 3;
    const int h    = blockIdx.y;
    const int qt   = blockIdx.x;
    const int qA   = qt * 64 + w * 16 + g;
    const int qB   = qA + 8;

    uint32_t bar[4];
#pragma unroll
    for (int i = 0; i < 4; i++) bar[i] = smem_u32(&s_bar[i]);
    const __half* Ksrc = g_Kp16 + (size_t)h * 64 * 4096;

    if (tid == 0) {
#pragma unroll
        for (int i = 0; i < 4; i++) mbar_init(bar[i], 1);
    }
    __syncthreads();

    if (tid == 0) {
#pragma unroll
        for (int i = 0; i < 4; i++) {
            mbar_arrive_expect(bar[i], 8192);
            bulk_g2s(smem_u32(&sK[i][0]), Ksrc + (size_t)i * 4096, 8192, bar[i]);
        }
    }

    uint32_t a[4][4];
    {
        const float* QA = g_Qh + ((size_t)h * N_NODES + qA) * 64;
        const float* QB = QA + 8 * 64;
#pragma unroll
        for (int s = 0; s < 4; s++) {
            const int c = s * 16 + 2 * l4;
            a[s][0] = pack_h2(QA[c],     QA[c + 1]);
            a[s][1] = pack_h2(QB[c],     QB[c + 1]);
            a[s][2] = pack_h2(QA[c + 8], QA[c + 9]);
            a[s][3] = pack_h2(QB[c + 8], QB[c + 9]);
        }
    }

    float bestA = -3.3e38f, best2A = -3.3e38f;
    float bestB = -3.3e38f, best2B = -3.3e38f;
    int   bkA = 0, bkB = 0;

    unsigned cw0A = g_adjbits[0 * N_NODES + qA];
    unsigned cw1A = g_adjbits[1 * N_NODES + qA];
    unsigned cw0B = g_adjbits[0 * N_NODES + qB];
    unsigned cw1B = g_adjbits[1 * N_NODES + qB];

    for (int t = 0; t < 64; t++) {
        const int buf = t & 3;
        const int ph  = (t >> 2) & 1;

        float acc[8][4];
#pragma unroll
        for (int nf = 0; nf < 8; nf++) {
            const unsigned wdA = (nf < 4) ? cw0A : cw1A;
            const unsigned wdB = (nf < 4) ? cw0B : cw1B;
            const int sh = (nf & 3) * 8 + l4 * 2;
            acc[nf][0] = ((wdA >> sh) & 1u)       ? 0.0f : -3e38f;
            acc[nf][1] = ((wdA >> (sh + 1)) & 1u) ? 0.0f : -3e38f;
            acc[nf][2] = ((wdB >> sh) & 1u)       ? 0.0f : -3e38f;
            acc[nf][3] = ((wdB >> (sh + 1)) & 1u) ? 0.0f : -3e38f;
        }
        if (t + 1 < 64) {
            cw0A = g_adjbits[(size_t)(2 * t + 2) * N_NODES + qA];
            cw1A = g_adjbits[(size_t)(2 * t + 3) * N_NODES + qA];
            cw0B = g_adjbits[(size_t)(2 * t + 2) * N_NODES + qB];
            cw1B = g_adjbits[(size_t)(2 * t + 3) * N_NODES + qB];
        }

        mbar_wait(bar[buf], ph);
        const __half* kb = &sK[buf][0];
#pragma unroll
        for (int nf = 0; nf < 8; nf++) {
#pragma unroll
            for (int sp = 0; sp < 2; sp++) {
                const uint4 bb = *(const uint4*)&kb[(size_t)(((nf * 2 + sp) * 32 + lane)) * 8];
                mma16(acc[nf], a[2 * sp],     bb.x, bb.y);
                mma16(acc[nf], a[2 * sp + 1], bb.z, bb.w);
            }
        }
        __syncthreads();
        if (tid == 0 && t + 4 < 64) {
            mbar_arrive_expect(bar[buf], 8192);
            bulk_g2s(smem_u32(&sK[buf][0]), Ksrc + (size_t)(t + 4) * 4096, 8192, bar[buf]);
        }

        float tA = fmaxf(acc[0][0], acc[0][1]);
        float tB = fmaxf(acc[0][2], acc[0][3]);
#pragma unroll
        for (int nf = 1; nf < 8; nf++) {
            tA = fmaxf(tA, fmaxf(acc[nf][0], acc[nf][1]));
            tB = fmaxf(tB, fmaxf(acc[nf][2], acc[nf][3]));
        }
        if (tA > bestA) rare2(acc, 0, t, l4, tA, bestA, best2A, bkA);
        else            best2A = fmaxf(best2A, tA);
        if (tB > bestB) rare2(acc, 2, t, l4, tB, bestB, best2B, bkB);
        else            best2B = fmaxf(best2B, tB);
    }

#pragma unroll
    for (int off = 1; off < 4; off <<= 1) {
        float ob  = __shfl_xor_sync(0xffffffffu, bestA, off);
        int   obk = __shfl_xor_sync(0xffffffffu, bkA,  off);
        float ob2 = __shfl_xor_sync(0xffffffffu, best2A, off);
        best2A = fmaxf(fmaxf(best2A, ob2), fminf(bestA, ob));
        if (ob > bestA || (ob == bestA && obk < bkA)) { bestA = ob; bkA = obk; }

        ob  = __shfl_xor_sync(0xffffffffu, bestB, off);
        obk = __shfl_xor_sync(0xffffffffu, bkB,  off);
        ob2 = __shfl_xor_sync(0xffffffffu, best2B, off);
        best2B = fmaxf(fmaxf(best2B, ob2), fminf(bestB, ob));
        if (ob > bestB || (ob == bestB && obk < bkB)) { bestB = ob; bkB = obk; }
    }

    if (l4 == 0) {
        const int hqA = h * N_NODES + qA;
        const int hqB = h * N_NODES + qB;
        g_argmax[hqA] = bkA;
        g_argmax[hqB] = bkB;
        if (bestA - best2A < BAND) g_fixlist[atomicAdd(&g_fixcount, 1)] = hqA;
        if (bestB - best2B < BAND) g_fixlist[atomicAdd(&g_fixcount, 1)] = hqB;
    }
}

// ============================================================================
// Pass 2: exact fp32 re-argmax of flagged rows — coalesced via K^T.
// ============================================================================
__global__ __launch_bounds__(512) void rescan() {
    __shared__ float sq[64];
    __shared__ float s_best[16];
    __shared__ int   s_bk[16];
    const int nfix = g_fixcount;
    const int tid = threadIdx.x, lane = tid & 31, wrp = tid >> 5;

    for (int i = blockIdx.x; i < nfix; i += gridDim.x) {
        const int hq = g_fixlist[i];
        const int h = hq >> 12, q = hq & (N_NODES - 1);
        if (tid < 64) sq[tid] = g_Qh[((size_t)h * N_NODES + q) * 64 + tid];
        __syncthreads();

        const float4* KT = (const float4*)(g_KhT + (size_t)h * 64 * N_NODES);
        float acc[8] = {0.f, 0.f, 0.f, 0.f, 0.f, 0.f, 0.f, 0.f};
#pragma unroll 4
        for (int d = 0; d < 64; d++) {
            const float qd = sq[d];
            const float4 v0 = KT[(size_t)d * 1024 + tid];
            const float4 v1 = KT[(size_t)d * 1024 + 512 + tid];
            acc[0] += qd * v0.x; acc[1] += qd * v0.y;
            acc[2] += qd * v0.z; acc[3] += qd * v0.w;
            acc[4] += qd * v1.x; acc[5] += qd * v1.y;
            acc[6] += qd * v1.z; acc[7] += qd * v1.w;
        }

        const int k0 = tid * 4, k1 = 2048 + tid * 4;
        const unsigned w0 = g_adjbits[(size_t)(k0 >> 5) * N_NODES + q];
        const unsigned w1 = g_adjbits[(size_t)(k1 >> 5) * N_NODES + q];
        float best = -3e38f;
        int   bk   = 1 << 30;
#pragma unroll
        for (int j = 0; j < 4; j++) {
            if ((w0 >> ((k0 + j) & 31)) & 1u)
                if (acc[j] > best) { best = acc[j]; bk = k0 + j; }
        }
#pragma unroll
        for (int j = 0; j < 4; j++) {
            if ((w1 >> ((k1 + j) & 31)) & 1u)
                if (acc[4 + j] > best) { best = acc[4 + j]; bk = k1 + j; }
        }
#pragma unroll
        for (int off = 16; off > 0; off >>= 1) {
            float ob  = __shfl_xor_sync(0xffffffffu, best, off);
            int   obk = __shfl_xor_sync(0xffffffffu, bk, off);
            if (ob > best || (ob == best && obk < bk)) { best = ob; bk = obk; }
        }
        if (lane == 0) { s_best[wrp] = best; s_bk[wrp] = bk; }
        __syncthreads();
        if (tid == 0) {
            float b = s_best[0]; int k = s_bk[0];
#pragma unroll
            for (int j = 1; j < 16; j++)
                if (s_best[j] > b || (s_best[j] == b && s_bk[j] < k)) {
                    b = s_best[j]; k = s_bk[j];
                }
            g_argmax[hq] = k;
        }
        __syncthreads();
    }
}

// ============================================================================
// out[q, h*64+d] = V[argmax(h,q), h*64+d] / HEADS
// ============================================================================
__global__ __launch_bounds__(256) void gather_out(float* __restrict__ out) {
    const int idx = blockIdx.x * blockDim.x + threadIdx.x;
    const int q   = idx >> 7;
    const int c4  = idx & 127;
    const int h   = c4 >> 4;
    const int k   = g_argmax[h * N_NODES + q];
    float4 t = *(const float4*)&g_V[(size_t)k * 512 + c4 * 4];
    float4 v = make_float4(t.x * 0.125f, t.y * 0.125f, t.z * 0.125f, t.w * 0.125f);
    *(float4*)&out[(size_t)idx * 4] = v;
}

// ============================================================================
extern "C" void kernel_launch(void* const* d_in, const int* in_sizes, int n_in,
                              void* d_out, int out_size)
{
    const float* x   = (const float*)d_in[0];
    const int*   adj = (const int*)d_in[1];
    const float* WQ  = (const float*)d_in[2];
    const float* WK  = (const float*)d_in[3];
    const float* WV  = (const float*)d_in[4];
    float* out = (float*)d_out;

    cudaFuncSetAttribute(proj_mma,
                         cudaFuncAttributeMaxDynamicSharedMemorySize, VM_SMEM);

    prep_all<<<1216, 256>>>(x, WQ, WK, WV, adj);

    proj_mma<<<dim3(64, 24), 128, VM_SMEM>>>();

    score_mma<<<dim3(N_NODES / 64, HEADS), 128>>>();

    rescan<<<512, 512>>>();

    gather_out<<<(N_NODES * 512 / 4) / 256, 256>>>(out);
}

// round 17
// speedup vs baseline: 1.1213x; 1.0362x over previous
#include <cuda_runtime.h>
#include <cuda_fp16.h>
#include <cstdint>

#define N_NODES 4096
#define IN_FEAT 512
#define HEADS   8
#define HEAD_DIM 64
// Score path is SINGLE fp16 (Q and K): per-score error sigma ~6e-3, tails ~3e-2.
// 0.075 is the empirically validated band (zero flips across R7-R15).
#define BAND    0.075f

// ---------------- scratch (static device globals: no allocation) ------------
__device__ float    g_Qh[HEADS * N_NODES * 64];  // head-major [h][node][d]
__device__ float    g_KhT[HEADS * 64 * N_NODES]; // [h][d][node]  (rescan)
__device__ __half   g_Kp16[HEADS * 64 * 4096];   // fragment-PAIRED fp16 tile images
__device__ __half   g_xAhi[512 * 4096];          // A-frag images of x (hi), (nt,chunk)
__device__ __half   g_xAlo[512 * 4096];
__device__ __half   g_wBhi[3 * 64 * 4096];       // B-frag images of WQ|WK|WV (hi)
__device__ __half   g_wBlo[3 * 64 * 4096];
__device__ float    g_V[N_NODES * 512];          // node-major
__device__ unsigned g_adjbits[128 * N_NODES];    // [word][q]
__device__ int      g_argmax[HEADS * N_NODES];
__device__ int      g_fixcnt[HEADS];
__device__ int      g_fixlistH[HEADS][N_NODES];

// ---------------- mbarrier + bulk-copy helpers --------------------------------
__device__ __forceinline__ uint32_t smem_u32(const void* p) {
    uint32_t a;
    asm("{ .reg .u64 t; cvta.to.shared.u64 t, %1; cvt.u32.u64 %0, t; }"
        : "=r"(a) : "l"(p));
    return a;
}
__device__ __forceinline__ void mbar_init(uint32_t bar, uint32_t cnt) {
    asm volatile("mbarrier.init.shared.b64 [%0], %1;" :: "r"(bar), "r"(cnt) : "memory");
}
__device__ __forceinline__ void mbar_arrive_expect(uint32_t bar, uint32_t bytes) {
    asm volatile("mbarrier.arrive.expect_tx.shared.b64 _, [%0], %1;"
                 :: "r"(bar), "r"(bytes) : "memory");
}
__device__ __forceinline__ void bulk_g2s(uint32_t dst, const void* src,
                                         uint32_t bytes, uint32_t bar) {
    asm volatile(
        "cp.async.bulk.shared::cluster.global.mbarrier::complete_tx::bytes "
        "[%0], [%1], %2, [%3];"
        :: "r"(dst), "l"(src), "r"(bytes), "r"(bar) : "memory");
}
__device__ __forceinline__ void mbar_wait(uint32_t bar, uint32_t parity) {
    asm volatile(
        "{\n\t"
        ".reg .pred P;\n\t"
        "WL_%=:\n\t"
        "mbarrier.try_wait.parity.acquire.cta.shared::cta.b64 P, [%0], %1, 0x989680;\n\t"
        "@P bra WD_%=;\n\t"
        "bra WL_%=;\n\t"
        "WD_%=:\n\t"
        "}"
        :: "r"(bar), "r"(parity) : "memory");
}

// ---------------- fp16 MMA helpers --------------------------------------------
__device__ __forceinline__ uint32_t pack_h2(float x, float y) {
    __half2 v = __floats2half2_rn(x, y);
    return *reinterpret_cast<uint32_t*>(&v);
}
__device__ __forceinline__ void mma16(float* d, const uint32_t* a,
                                      uint32_t b0, uint32_t b1) {
    asm("mma.sync.aligned.m16n8k16.row.col.f32.f16.f16.f32 "
        "{%0,%1,%2,%3}, {%4,%5,%6,%7}, {%8,%9}, {%0,%1,%2,%3};"
        : "+f"(d[0]), "+f"(d[1]), "+f"(d[2]), "+f"(d[3])
        : "r"(a[0]), "r"(a[1]), "r"(a[2]), "r"(a[3]), "r"(b0), "r"(b1));
}
__device__ __forceinline__ float f16lo(float x) {
    return x - __half2float(__float2half_rn(x));
}

// ============================================================================
// prep_all: ONE launch.
//   b < 512  : A-frag hi/lo images of x
//   b < 704  : B-frag hi/lo images of W{Q,K,V}
//   b < 1216 : adj -> bitmask (8 q rows per block)
// ============================================================================
__global__ __launch_bounds__(256) void prep_all(const float* __restrict__ x,
                                                const float* __restrict__ WQ,
                                                const float* __restrict__ WK,
                                                const float* __restrict__ WV,
                                                const int* __restrict__ adj) {
    const int b = blockIdx.x;
    if (b == 0 && threadIdx.x < HEADS) g_fixcnt[threadIdx.x] = 0;

    if (b < 512) {
        const int nt = b >> 3, c = b & 7;
        __half2* dhi = (__half2*)(g_xAhi + (size_t)b * 4096);
        __half2* dlo = (__half2*)(g_xAlo + (size_t)b * 4096);
#pragma unroll
        for (int rep = 0; rep < 2; rep++) {
            const int it   = rep * 256 + threadIdx.x;
            const int w    = it >> 7;
            const int s    = (it >> 5) & 3;
            const int lane = it & 31;
            const int g    = lane >> 2, l4 = lane & 3;
            const int n0 = nt * 64 + w * 16 + g;
            const int n1 = n0 + 8;
            const int k0 = c * 64 + s * 16 + l4 * 2;
            const float* p0 = x + (size_t)n0 * 512 + k0;
            const float* p1 = x + (size_t)n1 * 512 + k0;
            float v[8] = {p0[0], p0[1], p1[0], p1[1], p0[8], p0[9], p1[8], p1[9]};
            dhi[it * 4 + 0] = __floats2half2_rn(v[0], v[1]);
            dhi[it * 4 + 1] = __floats2half2_rn(v[2], v[3]);
            dhi[it * 4 + 2] = __floats2half2_rn(v[4], v[5]);
            dhi[it * 4 + 3] = __floats2half2_rn(v[6], v[7]);
            dlo[it * 4 + 0] = __floats2half2_rn(f16lo(v[0]), f16lo(v[1]));
            dlo[it * 4 + 1] = __floats2half2_rn(f16lo(v[2]), f16lo(v[3]));
            dlo[it * 4 + 2] = __floats2half2_rn(f16lo(v[4]), f16lo(v[5]));
            dlo[it * 4 + 3] = __floats2half2_rn(f16lo(v[6]), f16lo(v[7]));
        }
    } else if (b < 704) {
        const int b2 = b - 512;
        const int wsel = b2 >> 6;               // 0=Q,1=K,2=V
        const int r  = b2 & 63;
        const int ct = r >> 3, c = r & 7;
        const float* W = (wsel == 0) ? WQ : ((wsel == 1) ? WK : WV);
        __half2* dhi = (__half2*)(g_wBhi + (size_t)b2 * 4096);
        __half2* dlo = (__half2*)(g_wBlo + (size_t)b2 * 4096);
#pragma unroll
        for (int rep = 0; rep < 2; rep++) {
            const int it   = rep * 256 + threadIdx.x;
            const int lane = it & 31;
            const int sp   = (it >> 5) & 1;
            const int nf   = it >> 6;
            const int key  = nf * 8 + (lane >> 2);
            const int kc   = sp * 32 + (lane & 3) * 2;
            const float* p = W + (size_t)(ct * 64 + key) * 512 + c * 64 + kc;
            float v[8] = {p[0], p[1], p[8], p[9], p[16], p[17], p[24], p[25]};
            dhi[it * 4 + 0] = __floats2half2_rn(v[0], v[1]);
            dhi[it * 4 + 1] = __floats2half2_rn(v[2], v[3]);
            dhi[it * 4 + 2] = __floats2half2_rn(v[4], v[5]);
            dhi[it * 4 + 3] = __floats2half2_rn(v[6], v[7]);
            dlo[it * 4 + 0] = __floats2half2_rn(f16lo(v[0]), f16lo(v[1]));
            dlo[it * 4 + 1] = __floats2half2_rn(f16lo(v[2]), f16lo(v[3]));
            dlo[it * 4 + 2] = __floats2half2_rn(f16lo(v[4]), f16lo(v[5]));
            dlo[it * 4 + 3] = __floats2half2_rn(f16lo(v[6]), f16lo(v[7]));
        }
    } else {
        const int q = (b - 704) * 8 + (threadIdx.x >> 5);
        const int lane = threadIdx.x & 31;
        const int* row = adj + (size_t)q * N_NODES;
#pragma unroll 4
        for (int w = 0; w < 128; w++) {
            unsigned m = __ballot_sync(0xffffffffu, row[w * 32 + lane] > 0);
            if (lane == 0) g_adjbits[w * N_NODES + q] = m;
        }
    }
}

// ============================================================================
// proj_mma: Q|K|V = x @ W^T via 3-chain split-fp16 MMA.
// Grid (nt 64, ct 24): ct 0-7 -> Q, 8-15 -> K (+Kp16 image +KhT), 16-23 -> V.
// ============================================================================
#define VM_SMEM (2 * 4 * 8192)

__global__ __launch_bounds__(128, 1) void proj_mma() {
    extern __shared__ __half vsm[];
    __shared__ __align__(8) unsigned long long s_bar[2];

    const int tid  = threadIdx.x;
    const int w    = tid >> 5;
    const int lane = tid & 31;
    const int g    = lane >> 2;
    const int l4   = lane & 3;
    const int nt   = blockIdx.x;
    const int ct   = blockIdx.y;
    const int wsel = ct >> 3;
    const int ct8  = ct & 7;

    const uint32_t bar0 = smem_u32(&s_bar[0]);
    const uint32_t bar1 = smem_u32(&s_bar[1]);
    if (tid == 0) { mbar_init(bar0, 1); mbar_init(bar1, 1); }
    __syncthreads();

    auto issue = [&](int c) {
        const int slot = c & 1;
        const uint32_t bar = slot ? bar1 : bar0;
        __half* base = vsm + (size_t)slot * 4 * 4096;
        const size_t bi = (size_t)((wsel * 8 + ct8) * 8 + c) * 4096;
        mbar_arrive_expect(bar, 32768);
        bulk_g2s(smem_u32(base),            g_xAhi + (size_t)(nt * 8 + c) * 4096, 8192, bar);
        bulk_g2s(smem_u32(base + 4096),     g_xAlo + (size_t)(nt * 8 + c) * 4096, 8192, bar);
        bulk_g2s(smem_u32(base + 2 * 4096), g_wBhi + bi, 8192, bar);
        bulk_g2s(smem_u32(base + 3 * 4096), g_wBlo + bi, 8192, bar);
    };
    if (tid == 0) { issue(0); issue(1); }

    float acc[8][4];
#pragma unroll
    for (int nf = 0; nf < 8; nf++)
#pragma unroll
        for (int j = 0; j < 4; j++) acc[nf][j] = 0.f;

    for (int c = 0; c < 8; c++) {
        const int slot = c & 1;
        mbar_wait(slot ? bar1 : bar0, (c >> 1) & 1);
        const __half* Ah = vsm + (size_t)slot * 4 * 4096;
        const __half* Al = Ah + 4096;
        const __half* Bh = Ah + 2 * 4096;
        const __half* Bl = Ah + 3 * 4096;

        uint32_t ah[4][4], al[4][4];
#pragma unroll
        for (int s = 0; s < 4; s++) {
            const uint4 vh = *(const uint4*)&Ah[((w * 4 + s) * 32 + lane) * 8];
            ah[s][0] = vh.x; ah[s][1] = vh.y; ah[s][2] = vh.z; ah[s][3] = vh.w;
            const uint4 vl = *(const uint4*)&Al[((w * 4 + s) * 32 + lane) * 8];
            al[s][0] = vl.x; al[s][1] = vl.y; al[s][2] = vl.z; al[s][3] = vl.w;
        }

#pragma unroll
        for (int nf = 0; nf < 8; nf++) {
#pragma unroll
            for (int sp = 0; sp < 2; sp++) {
                const uint4 bh = *(const uint4*)&Bh[(size_t)(((nf * 2 + sp) * 32 + lane)) * 8];
                const uint4 bl = *(const uint4*)&Bl[(size_t)(((nf * 2 + sp) * 32 + lane)) * 8];
                mma16(acc[nf], ah[2 * sp],     bh.x, bh.y);
                mma16(acc[nf], ah[2 * sp + 1], bh.z, bh.w);
                mma16(acc[nf], al[2 * sp],     bh.x, bh.y);
                mma16(acc[nf], al[2 * sp + 1], bh.z, bh.w);
                mma16(acc[nf], ah[2 * sp],     bl.x, bl.y);
                mma16(acc[nf], ah[2 * sp + 1], bl.z, bl.w);
            }
        }
        __syncthreads();
        if (tid == 0 && c + 2 < 8) issue(c + 2);
    }

    const int n0 = nt * 64 + w * 16 + g;
    const int n1 = n0 + 8;

    if (wsel == 2) {
        // V: node-major [node][512]
#pragma unroll
        for (int nf = 0; nf < 8; nf++) {
            const int colv = ct8 * 64 + nf * 8 + l4 * 2;
            *(float2*)&g_V[(size_t)n0 * 512 + colv] = make_float2(acc[nf][0], acc[nf][1]);
            *(float2*)&g_V[(size_t)n1 * 512 + colv] = make_float2(acc[nf][2], acc[nf][3]);
        }
    } else if (wsel == 0) {
        // Q: head-major [h][node][d]
        float* dst = g_Qh + (size_t)ct8 * N_NODES * 64;
#pragma unroll
        for (int nf = 0; nf < 8; nf++) {
            const int d = nf * 8 + l4 * 2;
            *(float2*)&dst[(size_t)n0 * 64 + d] = make_float2(acc[nf][0], acc[nf][1]);
            *(float2*)&dst[(size_t)n1 * 64 + d] = make_float2(acc[nf][2], acc[nf][3]);
        }
    } else {
        // K: Kp16 fragment image (score) + KhT transposed fp32 (rescan)
        __half2* img = (__half2*)(g_Kp16 + (size_t)(ct8 * 64 + nt) * 4096);
        float*   kt  = g_KhT + (size_t)ct8 * 64 * N_NODES;
#pragma unroll
        for (int nf = 0; nf < 8; nf++) {
            const int jj  = nf & 3;
            const int sp_ = nf >> 2;
            const int kk0 = w * 16 + g;
            const int kk1 = kk0 + 8;
            const int lane0 = ((kk0 & 7) << 2) | l4;
            const int lane1 = ((kk1 & 7) << 2) | l4;
            const int idx0 = (((kk0 >> 3) * 2 + sp_) * 32 + lane0) * 4 + jj;
            const int idx1 = (((kk1 >> 3) * 2 + sp_) * 32 + lane1) * 4 + jj;
            img[idx0] = __floats2half2_rn(acc[nf][0], acc[nf][1]);
            img[idx1] = __floats2half2_rn(acc[nf][2], acc[nf][3]);

            const int d = nf * 8 + l4 * 2;
            kt[(size_t)d * N_NODES + n0]       = acc[nf][0];
            kt[(size_t)(d + 1) * N_NODES + n0] = acc[nf][1];
            kt[(size_t)d * N_NODES + n1]       = acc[nf][2];
            kt[(size_t)(d + 1) * N_NODES + n1] = acc[nf][3];
        }
    }
}

// ============================================================================
// rare index recovery (validated)
// ============================================================================
__device__ __forceinline__ void rare2(const float (&acc)[8][4], int cofs,
                                      int t, int l4, float tmax,
                                      float& best, float& best2, int& bk) {
    float sec = -3e38f;
    int   idx = bk;
    bool  taken = false;
#pragma unroll
    for (int nf = 0; nf < 8; nf++)
#pragma unroll
        for (int c = 0; c < 2; c++) {
            const float v = acc[nf][cofs + c];
            if (v == tmax && !taken) {
                taken = true;
                idx = t * 64 + nf * 8 + l4 * 2 + c;
            } else {
                sec = fmaxf(sec, v);
            }
        }
    best2 = fmaxf(best2, fmaxf(best, sec));
    best  = tmax;
    bk    = idx;
}

// ============================================================================
// Score argmax via mma.sync m16n8k16.f16 (in-register mask expansion from
// adjbits, words prefetched 1 tile ahead).  Flags -> per-head buckets.
// ============================================================================
__global__ __launch_bounds__(128, 4) void score_mma() {
    __shared__ __align__(16) __half sK[4][4096];
    __shared__ __align__(8) unsigned long long s_bar[4];

    const int tid  = threadIdx.x;
    const int w    = tid >> 5;
    const int lane = tid & 31;
    const int g    = lane >> 2;
    const int l4   = lane & 3;
    const int h    = blockIdx.y;
    const int qt   = blockIdx.x;
    const int qA   = qt * 64 + w * 16 + g;
    const int qB   = qA + 8;

    uint32_t bar[4];
#pragma unroll
    for (int i = 0; i < 4; i++) bar[i] = smem_u32(&s_bar[i]);
    const __half* Ksrc = g_Kp16 + (size_t)h * 64 * 4096;

    if (tid == 0) {
#pragma unroll
        for (int i = 0; i < 4; i++) mbar_init(bar[i], 1);
    }
    __syncthreads();

    if (tid == 0) {
#pragma unroll
        for (int i = 0; i < 4; i++) {
            mbar_arrive_expect(bar[i], 8192);
            bulk_g2s(smem_u32(&sK[i][0]), Ksrc + (size_t)i * 4096, 8192, bar[i]);
        }
    }

    uint32_t a[4][4];
    {
        const float* QA = g_Qh + ((size_t)h * N_NODES + qA) * 64;
        const float* QB = QA + 8 * 64;
#pragma unroll
        for (int s = 0; s < 4; s++) {
            const int c = s * 16 + 2 * l4;
            a[s][0] = pack_h2(QA[c],     QA[c + 1]);
            a[s][1] = pack_h2(QB[c],     QB[c + 1]);
            a[s][2] = pack_h2(QA[c + 8], QA[c + 9]);
            a[s][3] = pack_h2(QB[c + 8], QB[c + 9]);
        }
    }

    float bestA = -3.3e38f, best2A = -3.3e38f;
    float bestB = -3.3e38f, best2B = -3.3e38f;
    int   bkA = 0, bkB = 0;

    unsigned cw0A = g_adjbits[0 * N_NODES + qA];
    unsigned cw1A = g_adjbits[1 * N_NODES + qA];
    unsigned cw0B = g_adjbits[0 * N_NODES + qB];
    unsigned cw1B = g_adjbits[1 * N_NODES + qB];

    for (int t = 0; t < 64; t++) {
        const int buf = t & 3;
        const int ph  = (t >> 2) & 1;

        float acc[8][4];
#pragma unroll
        for (int nf = 0; nf < 8; nf++) {
            const unsigned wdA = (nf < 4) ? cw0A : cw1A;
            const unsigned wdB = (nf < 4) ? cw0B : cw1B;
            const int sh = (nf & 3) * 8 + l4 * 2;
            acc[nf][0] = ((wdA >> sh) & 1u)       ? 0.0f : -3e38f;
            acc[nf][1] = ((wdA >> (sh + 1)) & 1u) ? 0.0f : -3e38f;
            acc[nf][2] = ((wdB >> sh) & 1u)       ? 0.0f : -3e38f;
            acc[nf][3] = ((wdB >> (sh + 1)) & 1u) ? 0.0f : -3e38f;
        }
        if (t + 1 < 64) {
            cw0A = g_adjbits[(size_t)(2 * t + 2) * N_NODES + qA];
            cw1A = g_adjbits[(size_t)(2 * t + 3) * N_NODES + qA];
            cw0B = g_adjbits[(size_t)(2 * t + 2) * N_NODES + qB];
            cw1B = g_adjbits[(size_t)(2 * t + 3) * N_NODES + qB];
        }

        mbar_wait(bar[buf], ph);
        const __half* kb = &sK[buf][0];
#pragma unroll
        for (int nf = 0; nf < 8; nf++) {
#pragma unroll
            for (int sp = 0; sp < 2; sp++) {
                const uint4 bb = *(const uint4*)&kb[(size_t)(((nf * 2 + sp) * 32 + lane)) * 8];
                mma16(acc[nf], a[2 * sp],     bb.x, bb.y);
                mma16(acc[nf], a[2 * sp + 1], bb.z, bb.w);
            }
        }
        __syncthreads();
        if (tid == 0 && t + 4 < 64) {
            mbar_arrive_expect(bar[buf], 8192);
            bulk_g2s(smem_u32(&sK[buf][0]), Ksrc + (size_t)(t + 4) * 4096, 8192, bar[buf]);
        }

        float tA = fmaxf(acc[0][0], acc[0][1]);
        float tB = fmaxf(acc[0][2], acc[0][3]);
#pragma unroll
        for (int nf = 1; nf < 8; nf++) {
            tA = fmaxf(tA, fmaxf(acc[nf][0], acc[nf][1]));
            tB = fmaxf(tB, fmaxf(acc[nf][2], acc[nf][3]));
        }
        if (tA > bestA) rare2(acc, 0, t, l4, tA, bestA, best2A, bkA);
        else            best2A = fmaxf(best2A, tA);
        if (tB > bestB) rare2(acc, 2, t, l4, tB, bestB, best2B, bkB);
        else            best2B = fmaxf(best2B, tB);
    }

#pragma unroll
    for (int off = 1; off < 4; off <<= 1) {
        float ob  = __shfl_xor_sync(0xffffffffu, bestA, off);
        int   obk = __shfl_xor_sync(0xffffffffu, bkA,  off);
        float ob2 = __shfl_xor_sync(0xffffffffu, best2A, off);
        best2A = fmaxf(fmaxf(best2A, ob2), fminf(bestA, ob));
        if (ob > bestA || (ob == bestA && obk < bkA)) { bestA = ob; bkA = obk; }

        ob  = __shfl_xor_sync(0xffffffffu, bestB, off);
        obk = __shfl_xor_sync(0xffffffffu, bkB,  off);
        ob2 = __shfl_xor_sync(0xffffffffu, best2B, off);
        best2B = fmaxf(fmaxf(best2B, ob2), fminf(bestB, ob));
        if (ob > bestB || (ob == bestB && obk < bkB)) { bestB = ob; bkB = obk; }
    }

    if (l4 == 0) {
        g_argmax[h * N_NODES + qA] = bkA;
        g_argmax[h * N_NODES + qB] = bkB;
        if (bestA - best2A < BAND) g_fixlistH[h][atomicAdd(&g_fixcnt[h], 1)] = qA;
        if (bestB - best2B < BAND) g_fixlistH[h][atomicAdd(&g_fixcnt[h], 1)] = qB;
    }
}

// ============================================================================
// Pass 2: exact fp32 re-argmax.  Block = (head, group of 8 flagged rows):
// 8 Q rows in smem, ONE K^T stream per group (L2 traffic / 8), acc[8][8].
// Per-row FMA order and lowest-index tie-break identical to the R15 rescan.
// ============================================================================
__global__ __launch_bounds__(512) void rescan() {
    __shared__ float sq[8][64];
    __shared__ int   s_q[8];
    __shared__ float s_best[8][16];
    __shared__ int   s_bk[8][16];

    const int h   = blockIdx.y;
    const int cnt = g_fixcnt[h];
    const int tid = threadIdx.x, lane = tid & 31, wrp = tid >> 5;
    const float4* KT = (const float4*)(g_KhT + (size_t)h * 64 * N_NODES);

    for (int grp = blockIdx.x; grp * 8 < cnt; grp += gridDim.x) {
        if (tid < 8) {
            const int idx = grp * 8 + tid;
            s_q[tid] = g_fixlistH[h][(idx < cnt) ? idx : grp * 8];
        }
        __syncthreads();
        {
            const int j = tid >> 6, d = tid & 63;
            sq[j][d] = g_Qh[((size_t)h * N_NODES + s_q[j]) * 64 + d];
        }
        __syncthreads();

        float acc[8][8];
#pragma unroll
        for (int j = 0; j < 8; j++)
#pragma unroll
            for (int c = 0; c < 8; c++) acc[j][c] = 0.f;

#pragma unroll 4
        for (int d = 0; d < 64; d++) {
            const float4 v0 = KT[(size_t)d * 1024 + tid];
            const float4 v1 = KT[(size_t)d * 1024 + 512 + tid];
#pragma unroll
            for (int j = 0; j < 8; j++) {
                const float qd = sq[j][d];
                acc[j][0] += qd * v0.x; acc[j][1] += qd * v0.y;
                acc[j][2] += qd * v0.z; acc[j][3] += qd * v0.w;
                acc[j][4] += qd * v1.x; acc[j][5] += qd * v1.y;
                acc[j][6] += qd * v1.z; acc[j][7] += qd * v1.w;
            }
        }

        const int k0 = tid * 4, k1 = 2048 + tid * 4;
#pragma unroll
        for (int j = 0; j < 8; j++) {
            const int q = s_q[j];
            const unsigned w0 = g_adjbits[(size_t)(k0 >> 5) * N_NODES + q];
            const unsigned w1 = g_adjbits[(size_t)(k1 >> 5) * N_NODES + q];
            float best = -3e38f;
            int   bk   = 1 << 30;
#pragma unroll
            for (int c = 0; c < 4; c++) {
                if ((w0 >> ((k0 + c) & 31)) & 1u)
                    if (acc[j][c] > best) { best = acc[j][c]; bk = k0 + c; }
            }
#pragma unroll
            for (int c = 0; c < 4; c++) {
                if ((w1 >> ((k1 + c) & 31)) & 1u)
                    if (acc[j][4 + c] > best) { best = acc[j][4 + c]; bk = k1 + c; }
            }
#pragma unroll
            for (int off = 16; off > 0; off >>= 1) {
                float ob  = __shfl_xor_sync(0xffffffffu, best, off);
                int   obk = __shfl_xor_sync(0xffffffffu, bk, off);
                if (ob > best || (ob == best && obk < bk)) { best = ob; bk = obk; }
            }
            if (lane == 0) { s_best[j][wrp] = best; s_bk[j][wrp] = bk; }
        }
        __syncthreads();
        if (tid < 8) {
            const int j = tid;
            float b = s_best[j][0]; int k = s_bk[j][0];
#pragma unroll
            for (int m = 1; m < 16; m++)
                if (s_best[j][m] > b || (s_best[j][m] == b && s_bk[j][m] < k)) {
                    b = s_best[j][m]; k = s_bk[j][m];
                }
            g_argmax[h * N_NODES + s_q[j]] = k;
        }
        __syncthreads();
    }
}

// ============================================================================
// out[q, h*64+d] = V[argmax(h,q), h*64+d] / HEADS
// ============================================================================
__global__ __launch_bounds__(256) void gather_out(float* __restrict__ out) {
    const int idx = blockIdx.x * blockDim.x + threadIdx.x;
    const int q   = idx >> 7;
    const int c4  = idx & 127;
    const int h   = c4 >> 4;
    const int k   = g_argmax[h * N_NODES + q];
    float4 t = *(const float4*)&g_V[(size_t)k * 512 + c4 * 4];
    float4 v = make_float4(t.x * 0.125f, t.y * 0.125f, t.z * 0.125f, t.w * 0.125f);
    *(float4*)&out[(size_t)idx * 4] = v;
}

// ============================================================================
extern "C" void kernel_launch(void* const* d_in, const int* in_sizes, int n_in,
                              void* d_out, int out_size)
{
    const float* x   = (const float*)d_in[0];
    const int*   adj = (const int*)d_in[1];
    const float* WQ  = (const float*)d_in[2];
    const float* WK  = (const float*)d_in[3];
    const float* WV  = (const float*)d_in[4];
    float* out = (float*)d_out;

    cudaFuncSetAttribute(proj_mma,
                         cudaFuncAttributeMaxDynamicSharedMemorySize, VM_SMEM);

    prep_all<<<1216, 256>>>(x, WQ, WK, WV, adj);

    proj_mma<<<dim3(64, 24), 128, VM_SMEM>>>();

    score_mma<<<dim3(N_NODES / 64, HEADS), 128>>>();

    rescan<<<dim3(64, HEADS), 512>>>();

    gather_out<<<(N_NODES * 512 / 4) / 256, 256>>>(out);
}